// round 6
// baseline (speedup 1.0000x reference)
#include <cuda_runtime.h>
#include <math.h>
#include <stdint.h>

#define N_NODES 20000
#define N_EDGES 320000
#define T_STEPS 16
#define HG 64
#define HT 128
#define G3 384
#define NT (N_NODES * T_STEPS)
#define LN_EPS 1e-5f

// ===================== scratch (static device globals) =======================
__device__ int   g_cnt[N_NODES];
__device__ int   g_fill[N_NODES];
__device__ int   g_rowptr[N_NODES + 1];
__device__ int   g_col[N_EDGES];
__device__ float g_ws1[HG * 2 * HG];        // stacked [Wl1;Wr1]: (out=64, K=128)
__device__ float g_h0_all[NT * HG];
__device__ float g_ins_all[NT * (2 * HG)];  // sage1 input: [agg(64) | h0(64)]
__device__ float g_H_all[NT * HG];
__device__ float g_gi_all[NT * G3];
__device__ float g_hid[N_NODES * HT];

__device__ __forceinline__ float warp_sum(float v) {
#pragma unroll
    for (int o = 16; o; o >>= 1) v += __shfl_xor_sync(0xFFFFFFFFu, v, o);
    return v;
}

// 3xTF32 split: hi = tf32(v), lo = tf32(v - hi)
__device__ __forceinline__ void split_tf(float v, uint32_t& hi, uint32_t& lo) {
    uint32_t h;
    asm("cvt.rna.tf32.f32 %0, %1;" : "=r"(h) : "f"(v));
    float r = v - __uint_as_float(h);
    uint32_t l;
    asm("cvt.rna.tf32.f32 %0, %1;" : "=r"(l) : "f"(r));
    hi = h; lo = l;
}

// m16n8k8 tf32 MMA (sm_80+ generic PTX — compiles at compute_103)
__device__ __forceinline__ void mma8(float* d, const uint32_t* a, uint32_t b0, uint32_t b1) {
    asm volatile(
        "mma.sync.aligned.m16n8k8.row.col.f32.tf32.tf32.f32 "
        "{%0,%1,%2,%3}, {%4,%5,%6,%7}, {%8,%9}, {%0,%1,%2,%3};"
        : "+f"(d[0]), "+f"(d[1]), "+f"(d[2]), "+f"(d[3])
        : "r"(a[0]), "r"(a[1]), "r"(a[2]), "r"(a[3]), "r"(b0), "r"(b1));
}

// ------------------------- init / CSR build ---------------------------------
__global__ void k_zero_all() {
    int idx = blockIdx.x * blockDim.x + threadIdx.x;
    if (idx < N_NODES * HT) g_hid[idx] = 0.f;
    if (idx < N_NODES) { g_cnt[idx] = 0; g_fill[idx] = 0; }
}

__global__ void k_hist(const int* __restrict__ ei) {
    int e = blockIdx.x * blockDim.x + threadIdx.x;
    if (e < N_EDGES) atomicAdd(&g_cnt[ei[N_EDGES + e]], 1);
}

__global__ void k_scan() {
    __shared__ int sh[1024];
    __shared__ int base;
    int tid = threadIdx.x;
    if (tid == 0) { base = 0; g_rowptr[0] = 0; }
    __syncthreads();
    for (int start = 0; start < N_NODES; start += 1024) {
        int i = start + tid;
        int v = (i < N_NODES) ? g_cnt[i] : 0;
        sh[tid] = v;
        __syncthreads();
        for (int off = 1; off < 1024; off <<= 1) {
            int t = (tid >= off) ? sh[tid - off] : 0;
            __syncthreads();
            sh[tid] += t;
            __syncthreads();
        }
        if (i < N_NODES) g_rowptr[i + 1] = base + sh[tid];
        __syncthreads();
        if (tid == 1023) base += sh[1023];
        __syncthreads();
    }
}

__global__ void k_scatter(const int* __restrict__ ei) {
    int e = blockIdx.x * blockDim.x + threadIdx.x;
    if (e >= N_EDGES) return;
    int d = ei[N_EDGES + e];
    int p = atomicAdd(&g_fill[d], 1);
    g_col[g_rowptr[d] + p] = ei[e];
}

__global__ void k_prep_ws1(const float* __restrict__ Wl1, const float* __restrict__ Wr1) {
    int idx = blockIdx.x * blockDim.x + threadIdx.x;
    if (idx >= HG * 2 * HG) return;
    int m = idx >> 7, k = idx & 127;
    g_ws1[idx] = (k < HG) ? Wl1[k * HG + m] : Wr1[(k - HG) * HG + m];
}

// ------------------- layer 0 (batched): agg + SAGE + LN + relu --------------
__global__ void k_stack0_all(const float* __restrict__ x_seq,
                             const float* __restrict__ Wl, const float* __restrict__ Wr,
                             const float* __restrict__ b0,
                             const float* __restrict__ g, const float* __restrict__ beta) {
    int t = blockIdx.y;
    int n = blockIdx.x * 8 + (threadIdx.x >> 5);
    int lane = threadIdx.x & 31;
    if (n >= N_NODES) return;
    const float* xt = x_seq + t * N_NODES;
    int beg = g_rowptr[n], end = g_rowptr[n + 1];
    float acc = 0.f;
    for (int i = beg + lane; i < end; i += 32) acc += xt[g_col[i]];
    acc = warp_sum(acc);
    float deg = fmaxf((float)(end - beg), 1.f);
    float agg = acc / deg;
    float xv = xt[n];
    float v0 = agg * Wl[lane]      + xv * Wr[lane]      + b0[lane];
    float v1 = agg * Wl[lane + 32] + xv * Wr[lane + 32] + b0[lane + 32];
    float mu = warp_sum(v0 + v1) * (1.f / 64.f);
    float d0 = v0 - mu, d1 = v1 - mu;
    float var = warp_sum(d0 * d0 + d1 * d1) * (1.f / 64.f);
    float inv = rsqrtf(var + LN_EPS);
    float h0a = fmaxf(d0 * inv * g[lane]      + beta[lane], 0.f);
    float h0b = fmaxf(d1 * inv * g[lane + 32] + beta[lane + 32], 0.f);
    size_t row = (size_t)t * N_NODES + n;
    g_h0_all[row * HG + lane]      = h0a;
    g_h0_all[row * HG + lane + 32] = h0b;
    g_ins_all[row * 128 + 64 + lane]      = h0a;
    g_ins_all[row * 128 + 64 + lane + 32] = h0b;
}

// ------------------- layer 1 aggregate (batched) -----------------------------
__global__ void k_agg1_all() {
    int t = blockIdx.y;
    int n = blockIdx.x * 8 + (threadIdx.x >> 5);
    int lane = threadIdx.x & 31;
    if (n >= N_NODES) return;
    const float* h0t = g_h0_all + (size_t)t * N_NODES * HG;
    int beg = g_rowptr[n], end = g_rowptr[n + 1];
    float a0 = 0.f, a1 = 0.f;
    for (int i = beg; i < end; i++) {
        int s = g_col[i];
        a0 += h0t[s * HG + lane];
        a1 += h0t[s * HG + lane + 32];
    }
    float inv = 1.f / fmaxf((float)(end - beg), 1.f);
    size_t row = (size_t)t * N_NODES + n;
    g_ins_all[row * 128 + lane]      = a0 * inv;
    g_ins_all[row * 128 + lane + 32] = a1 * inv;
}

// ===================== 3xTF32 mma.sync GEMM kernels ===========================
// MODE 0: S = ins_all(NTx128) @ ws1^T(64x128);  epilogue: +b1, LN, relu -> g_H_all
// MODE 1: gi = H_all(NTx64) @ Wih^T(384x64);    epilogue: +bih -> g_gi_all
// MODE 2: gh = hid(Nx128) @ Whh^T(384x128);     epilogue: fused GRU -> g_hid
template <int MODE>
__global__ void __launch_bounds__(256, 1)
k_mma(const float* __restrict__ Wg, const float* __restrict__ bias,
      const float* __restrict__ p0, const float* __restrict__ p1, int t) {
    constexpr int K       = (MODE == 1) ? 64 : 128;
    constexpr int GATES   = (MODE == 2) ? 3 : 1;
    constexpr int BM      = 128;
    constexpr int BN      = (MODE == 1) ? 192 : 64;
    constexpr int WARPS_N = (MODE == 1) ? 4 : 2;
    constexpr int WM      = (MODE == 1) ? 64 : 32;   // BM / WARPS_M
    constexpr int WN      = BN / WARPS_N;
    constexpr int MF      = WM / 16;
    constexpr int NF      = WN / 8;
    constexpr int LDA     = K + 4;
    constexpr int BROWS   = BN * GATES;
    constexpr int ROWS    = (MODE == 2) ? N_NODES : NT;

    extern __shared__ float sm[];
    float* As = sm;                    // BM x LDA (raw fp32)
    float* Bs = sm + BM * LDA;         // BROWS x LDA (raw fp32)

    const float* A  = (MODE == 0) ? g_ins_all : (MODE == 1) ? g_H_all : g_hid;
    const float* Wm = (MODE == 0) ? g_ws1 : Wg;

    int tid = threadIdx.x;
    int rowBase = blockIdx.y * BM;
    int colBase = blockIdx.x * BN;

    // ---- stage A tile (raw fp32) ----
    for (int idx = tid; idx < BM * (K / 4); idx += 256) {
        int r = idx / (K / 4), c = (idx % (K / 4)) * 4;
        int gr = rowBase + r;
        float4 v = make_float4(0.f, 0.f, 0.f, 0.f);
        if (gr < ROWS) v = *(const float4*)(A + (size_t)gr * K + c);
        *(float4*)(As + r * LDA + c) = v;
    }
    // ---- stage B tile(s) (raw fp32) ----
    for (int idx = tid; idx < BROWS * (K / 4); idx += 256) {
        int r = idx / (K / 4), c = (idx % (K / 4)) * 4;
        int gr;
        if (MODE == 2) { int gate = r / BN, ln = r % BN; gr = gate * HT + colBase + ln; }
        else           { gr = colBase + r; }
        float4 v = *(const float4*)(Wm + (size_t)gr * K + c);
        *(float4*)(Bs + r * LDA + c) = v;
    }
    __syncthreads();

    int warp = tid >> 5, lane = tid & 31;
    int wm = warp / WARPS_N, wn = warp % WARPS_N;
    int g = lane >> 2, tg = lane & 3;
    int m0 = wm * WM, n0 = wn * WN;

    float acc[GATES][MF][NF][4] = {};

#pragma unroll
    for (int k0 = 0; k0 < K; k0 += 8) {
        uint32_t ah[MF][4], al[MF][4];
#pragma unroll
        for (int mf = 0; mf < MF; mf++) {
            const float* ap = As + (m0 + 16 * mf + g) * LDA + k0 + tg;
            split_tf(ap[0],           ah[mf][0], al[mf][0]);
            split_tf(ap[8 * LDA],     ah[mf][1], al[mf][1]);
            split_tf(ap[4],           ah[mf][2], al[mf][2]);
            split_tf(ap[8 * LDA + 4], ah[mf][3], al[mf][3]);
        }
#pragma unroll
        for (int gt = 0; gt < GATES; gt++) {
#pragma unroll
            for (int nf = 0; nf < NF; nf++) {
                const float* bp = Bs + (gt * BN + n0 + 8 * nf + g) * LDA + k0 + tg;
                uint32_t bh0, bl0, bh1, bl1;
                split_tf(bp[0], bh0, bl0);
                split_tf(bp[4], bh1, bl1);
#pragma unroll
                for (int mf = 0; mf < MF; mf++) {
                    mma8(acc[gt][mf][nf], al[mf], bh0, bh1);   // small terms first
                    mma8(acc[gt][mf][nf], ah[mf], bl0, bl1);
                    mma8(acc[gt][mf][nf], ah[mf], bh0, bh1);
                }
            }
        }
    }

    if (MODE == 0) {
        // ---- +bias into smem, then fused LN+relu ----
        __syncthreads();                       // done with As/Bs
        float* S = sm;                         // 128 x 68
#pragma unroll
        for (int mf = 0; mf < MF; mf++)
#pragma unroll
            for (int nf = 0; nf < NF; nf++) {
                int r = m0 + 16 * mf + g;
                int c = n0 + 8 * nf + 2 * tg;
                S[r * 68 + c]           = acc[0][mf][nf][0] + bias[c];
                S[r * 68 + c + 1]       = acc[0][mf][nf][1] + bias[c + 1];
                S[(r + 8) * 68 + c]     = acc[0][mf][nf][2] + bias[c];
                S[(r + 8) * 68 + c + 1] = acc[0][mf][nf][3] + bias[c + 1];
            }
        __syncthreads();
#pragma unroll
        for (int i = 0; i < 16; i++) {
            int r = warp * 16 + i;
            float v0 = S[r * 68 + lane];
            float v1 = S[r * 68 + lane + 32];
            float mu = warp_sum(v0 + v1) * (1.f / 64.f);
            float d0 = v0 - mu, d1 = v1 - mu;
            float var = warp_sum(d0 * d0 + d1 * d1) * (1.f / 64.f);
            float inv = rsqrtf(var + LN_EPS);
            size_t rowg = (size_t)rowBase + r;
            g_H_all[rowg * HG + lane]      = fmaxf(d0 * inv * p0[lane]      + p1[lane], 0.f);
            g_H_all[rowg * HG + lane + 32] = fmaxf(d1 * inv * p0[lane + 32] + p1[lane + 32], 0.f);
        }
    } else if (MODE == 1) {
        // ---- +bias, store gi (NT is an exact multiple of BM: no guards) ----
#pragma unroll
        for (int mf = 0; mf < MF; mf++)
#pragma unroll
            for (int nf = 0; nf < NF; nf++) {
                size_t r = (size_t)rowBase + m0 + 16 * mf + g;
                int c = colBase + n0 + 8 * nf + 2 * tg;
                float2 w0 = make_float2(acc[0][mf][nf][0] + bias[c],
                                        acc[0][mf][nf][1] + bias[c + 1]);
                float2 w1 = make_float2(acc[0][mf][nf][2] + bias[c],
                                        acc[0][mf][nf][3] + bias[c + 1]);
                *(float2*)(g_gi_all + r * G3 + c)       = w0;
                *(float2*)(g_gi_all + (r + 8) * G3 + c) = w1;
            }
    } else {
        // ---- fused GRU gates: h = (1-z)*n + z*h ----
#pragma unroll
        for (int mf = 0; mf < MF; mf++)
#pragma unroll
            for (int nf = 0; nf < NF; nf++) {
#pragma unroll
                for (int half = 0; half < 2; half++) {
                    int node = rowBase + m0 + 16 * mf + g + half * 8;
                    if (node >= N_NODES) continue;
                    int c = colBase + n0 + 8 * nf + 2 * tg;
                    const float* gi = g_gi_all + ((size_t)t * N_NODES + node) * G3;
                    float2 gir = *(const float2*)(gi + c);
                    float2 giz = *(const float2*)(gi + 128 + c);
                    float2 gin = *(const float2*)(gi + 256 + c);
                    float hr0 = acc[0][mf][nf][half * 2 + 0] + bias[c];
                    float hr1 = acc[0][mf][nf][half * 2 + 1] + bias[c + 1];
                    float hz0 = acc[1][mf][nf][half * 2 + 0] + bias[128 + c];
                    float hz1 = acc[1][mf][nf][half * 2 + 1] + bias[128 + c + 1];
                    float hn0 = acc[2][mf][nf][half * 2 + 0] + bias[256 + c];
                    float hn1 = acc[2][mf][nf][half * 2 + 1] + bias[256 + c + 1];
                    float* hid = g_hid + (size_t)node * HT + c;
                    float2 h = *(float2*)hid;
                    float r0 = 1.f / (1.f + __expf(-(gir.x + hr0)));
                    float r1 = 1.f / (1.f + __expf(-(gir.y + hr1)));
                    float z0 = 1.f / (1.f + __expf(-(giz.x + hz0)));
                    float z1 = 1.f / (1.f + __expf(-(giz.y + hz1)));
                    float n0v = tanhf(gin.x + r0 * hn0);
                    float n1v = tanhf(gin.y + r1 * hn1);
                    h.x = (1.f - z0) * n0v + z0 * h.x;
                    h.y = (1.f - z1) * n1v + z1 * h.y;
                    *(float2*)hid = h;
                }
            }
    }
}

// ------------------- output head ---------------------------------------------
__global__ void k_head(const float* __restrict__ W, const float* __restrict__ b,
                       float* __restrict__ y) {
    int warp = (blockIdx.x * blockDim.x + threadIdx.x) >> 5;
    int lane = threadIdx.x & 31;
    if (warp >= N_NODES) return;
    float acc = 0.f;
#pragma unroll
    for (int i = 0; i < 4; i++) {
        int j = lane + 32 * i;
        acc += g_hid[warp * HT + j] * W[j];
    }
    acc = warp_sum(acc);
    if (lane == 0) y[warp] = acc + b[0];
}

// ------------------------- launch ---------------------------------------------
extern "C" void kernel_launch(void* const* d_in, const int* in_sizes, int n_in,
                              void* d_out, int out_size) {
    const float* x_seq = (const float*)d_in[0];
    const int*   ei    = (const int*)d_in[1];
    const float* W_l0  = (const float*)d_in[2];
    const float* W_r0  = (const float*)d_in[3];
    const float* b0    = (const float*)d_in[4];
    const float* ln0g  = (const float*)d_in[5];
    const float* ln0b  = (const float*)d_in[6];
    const float* W_l1  = (const float*)d_in[7];
    const float* W_r1  = (const float*)d_in[8];
    const float* b1    = (const float*)d_in[9];
    const float* ln1g  = (const float*)d_in[10];
    const float* ln1b  = (const float*)d_in[11];
    const float* Wih   = (const float*)d_in[12];
    const float* Whh   = (const float*)d_in[13];
    const float* bih   = (const float*)d_in[14];
    const float* bhh   = (const float*)d_in[15];
    const float* headW = (const float*)d_in[16];
    const float* headb = (const float*)d_in[17];
    float* y = (float*)d_out;

    const int SMEM0 = (128 * 132 + 64 * 132) * 4;        // 101376
    const int SMEM1 = (128 * 68 + 192 * 68) * 4;         //  87040
    const int SMEM2 = (128 * 132 + 192 * 132) * 4;       // 168960
    cudaFuncSetAttribute(k_mma<0>, cudaFuncAttributeMaxDynamicSharedMemorySize, SMEM0);
    cudaFuncSetAttribute(k_mma<1>, cudaFuncAttributeMaxDynamicSharedMemorySize, SMEM1);
    cudaFuncSetAttribute(k_mma<2>, cudaFuncAttributeMaxDynamicSharedMemorySize, SMEM2);

    k_zero_all<<<(N_NODES * HT + 255) / 256, 256>>>();
    k_hist<<<(N_EDGES + 255) / 256, 256>>>(ei);
    k_scan<<<1, 1024>>>();
    k_scatter<<<(N_EDGES + 255) / 256, 256>>>(ei);
    k_prep_ws1<<<(HG * 2 * HG + 255) / 256, 256>>>(W_l1, W_r1);

    dim3 gridA((N_NODES + 7) / 8, T_STEPS);
    k_stack0_all<<<gridA, 256>>>(x_seq, W_l0, W_r0, b0, ln0g, ln0b);
    k_agg1_all<<<gridA, 256>>>();

    k_mma<0><<<dim3(1, NT / 128), 256, SMEM0>>>(nullptr, b1, ln1g, ln1b, 0);
    k_mma<1><<<dim3(G3 / 192, NT / 128), 256, SMEM1>>>(Wih, bih, nullptr, nullptr, 0);

    int gridGH = (N_NODES + 127) / 128;   // 157
    for (int t = 0; t < T_STEPS; t++)
        k_mma<2><<<dim3(2, gridGH), 256, SMEM2>>>(Whh, bhh, nullptr, nullptr, t);

    k_head<<<(N_NODES * 32 + 255) / 256, 256>>>(headW, headb, y);
}

// round 7
// speedup vs baseline: 1.2921x; 1.2921x over previous
#include <cuda_runtime.h>
#include <math.h>
#include <stdint.h>

#define N_NODES 20000
#define N_EDGES 320000
#define T_STEPS 16
#define HG 64
#define HT 128
#define G3 384
#define NT (N_NODES * T_STEPS)
#define LN_EPS 1e-5f

// ===================== scratch (static device globals) =======================
__device__ int   g_cnt[N_NODES];          // zero-init at load; k_scan re-zeroes
__device__ int   g_fill[N_NODES];
__device__ int   g_rowptr[N_NODES + 1];
__device__ int   g_col[N_EDGES];
__device__ float g_ws1[HG * 2 * HG];      // stacked [Wl1;Wr1]: (out=64, K=128)
__device__ float g_h0_all[NT * HG];
__device__ float g_ins_all[NT * (2 * HG)];
__device__ float g_H_all[NT * HG];
__device__ float g_gi_all[NT * G3];
__device__ float g_hid[N_NODES * HT];

__device__ __forceinline__ float warp_sum(float v) {
#pragma unroll
    for (int o = 16; o; o >>= 1) v += __shfl_xor_sync(0xFFFFFFFFu, v, o);
    return v;
}

// bf16x2 split: returns packed hi pair, writes packed lo pair (lo = v - hi)
__device__ __forceinline__ uint32_t pack_split(float x0, float x1, uint32_t& lo) {
    uint32_t hi;
    asm("cvt.rn.bf16x2.f32 %0, %1, %2;" : "=r"(hi) : "f"(x1), "f"(x0));
    float h0 = __uint_as_float(hi << 16);
    float h1 = __uint_as_float(hi & 0xFFFF0000u);
    float l0 = x0 - h0, l1 = x1 - h1;
    asm("cvt.rn.bf16x2.f32 %0, %1, %2;" : "=r"(lo) : "f"(l1), "f"(l0));
    return hi;
}

// m16n8k16 bf16 MMA (sm_80+ generic PTX)
__device__ __forceinline__ void mma16(float* d, const uint32_t* a, uint32_t b0, uint32_t b1) {
    asm volatile(
        "mma.sync.aligned.m16n8k16.row.col.f32.bf16.bf16.f32 "
        "{%0,%1,%2,%3}, {%4,%5,%6,%7}, {%8,%9}, {%0,%1,%2,%3};"
        : "+f"(d[0]), "+f"(d[1]), "+f"(d[2]), "+f"(d[3])
        : "r"(a[0]), "r"(a[1]), "r"(a[2]), "r"(a[3]), "r"(b0), "r"(b1));
}

// ------------------------- CSR build -----------------------------------------
__global__ void k_hist(const int* __restrict__ ei) {
    int e = blockIdx.x * blockDim.x + threadIdx.x;
    if (e < N_EDGES) atomicAdd(&g_cnt[ei[N_EDGES + e]], 1);
}

__global__ void k_scan() {
    __shared__ int sh[1024];
    __shared__ int base;
    int tid = threadIdx.x;
    if (tid == 0) { base = 0; g_rowptr[0] = 0; }
    __syncthreads();
    for (int start = 0; start < N_NODES; start += 1024) {
        int i = start + tid;
        int v = (i < N_NODES) ? g_cnt[i] : 0;
        sh[tid] = v;
        __syncthreads();
        for (int off = 1; off < 1024; off <<= 1) {
            int t = (tid >= off) ? sh[tid - off] : 0;
            __syncthreads();
            sh[tid] += t;
            __syncthreads();
        }
        if (i < N_NODES) g_rowptr[i + 1] = base + sh[tid];
        __syncthreads();
        if (tid == 1023) base += sh[1023];
        __syncthreads();
    }
    // re-zero counters for scatter (fill) and for the next graph replay (cnt)
    for (int i = tid; i < N_NODES; i += 1024) { g_cnt[i] = 0; g_fill[i] = 0; }
}

__global__ void k_scatter(const int* __restrict__ ei) {
    int e = blockIdx.x * blockDim.x + threadIdx.x;
    if (e >= N_EDGES) return;
    int d = ei[N_EDGES + e];
    int p = atomicAdd(&g_fill[d], 1);
    g_col[g_rowptr[d] + p] = ei[e];
}

__global__ void k_prep_ws1(const float* __restrict__ Wl1, const float* __restrict__ Wr1) {
    int idx = blockIdx.x * blockDim.x + threadIdx.x;
    if (idx >= HG * 2 * HG) return;
    int m = idx >> 7, k = idx & 127;
    g_ws1[idx] = (k < HG) ? Wl1[k * HG + m] : Wr1[(k - HG) * HG + m];
}

// ------------------- layer 0 (batched): agg + SAGE + LN + relu ---------------
__global__ void k_stack0_all(const float* __restrict__ x_seq,
                             const float* __restrict__ Wl, const float* __restrict__ Wr,
                             const float* __restrict__ b0,
                             const float* __restrict__ g, const float* __restrict__ beta) {
    int t = blockIdx.y;
    int n = blockIdx.x * 8 + (threadIdx.x >> 5);
    int lane = threadIdx.x & 31;
    if (n >= N_NODES) return;
    const float* xt = x_seq + t * N_NODES;
    int beg = g_rowptr[n], end = g_rowptr[n + 1];
    float acc = 0.f;
    for (int i = beg + lane; i < end; i += 32) acc += xt[g_col[i]];
    acc = warp_sum(acc);
    float deg = fmaxf((float)(end - beg), 1.f);
    float agg = acc / deg;
    float xv = xt[n];
    float v0 = agg * Wl[lane]      + xv * Wr[lane]      + b0[lane];
    float v1 = agg * Wl[lane + 32] + xv * Wr[lane + 32] + b0[lane + 32];
    float mu = warp_sum(v0 + v1) * (1.f / 64.f);
    float d0 = v0 - mu, d1 = v1 - mu;
    float var = warp_sum(d0 * d0 + d1 * d1) * (1.f / 64.f);
    float inv = rsqrtf(var + LN_EPS);
    float h0a = fmaxf(d0 * inv * g[lane]      + beta[lane], 0.f);
    float h0b = fmaxf(d1 * inv * g[lane + 32] + beta[lane + 32], 0.f);
    size_t row = (size_t)t * N_NODES + n;
    g_h0_all[row * HG + lane]      = h0a;
    g_h0_all[row * HG + lane + 32] = h0b;
    g_ins_all[row * 128 + 64 + lane]      = h0a;
    g_ins_all[row * 128 + 64 + lane + 32] = h0b;
}

// ------------------- layer 1 aggregate (batched) -----------------------------
__global__ void k_agg1_all() {
    int t = blockIdx.y;
    int n = blockIdx.x * 8 + (threadIdx.x >> 5);
    int lane = threadIdx.x & 31;
    if (n >= N_NODES) return;
    const float* h0t = g_h0_all + (size_t)t * N_NODES * HG;
    int beg = g_rowptr[n], end = g_rowptr[n + 1];
    float a0 = 0.f, a1 = 0.f;
    for (int i = beg; i < end; i++) {
        int s = g_col[i];
        a0 += h0t[s * HG + lane];
        a1 += h0t[s * HG + lane + 32];
    }
    float inv = 1.f / fmaxf((float)(end - beg), 1.f);
    size_t row = (size_t)t * N_NODES + n;
    g_ins_all[row * 128 + lane]      = a0 * inv;
    g_ins_all[row * 128 + lane + 32] = a1 * inv;
}

// ===================== bf16x3 mma.sync GEMM kernels ===========================
// MODE 0: S = ins_all(NTx128) @ ws1^T(64x128);  epilogue: +b1, LN, relu -> g_H_all
// MODE 1: gi = H_all(NTx64) @ Wih^T(384x64);    epilogue: +bih -> g_gi_all
// MODE 2: gh = hid(Nx128) @ Whh^T(384x128);     epilogue: fused GRU -> g_hid
template <int MODE>
__global__ void __launch_bounds__(256, 1)
k_mma(const float* __restrict__ Wg, const float* __restrict__ bias,
      const float* __restrict__ p0, const float* __restrict__ p1, int t) {
    constexpr int K       = (MODE == 1) ? 64 : 128;
    constexpr int K2      = K / 2;                    // u32 (bf16x2) columns
    constexpr int LDK     = K2 + 4;                   // LDK % 32 == 4 -> conflict-free
    constexpr int GATES   = (MODE == 2) ? 3 : 1;
    constexpr int BM      = 128;
    constexpr int BN      = (MODE == 1) ? 192 : 64;
    constexpr int WARPS_N = (MODE == 0) ? 2 : 4;
    constexpr int WM      = (MODE == 0) ? 32 : 64;
    constexpr int WN      = BN / WARPS_N;
    constexpr int MF      = WM / 16;
    constexpr int NF      = WN / 8;
    constexpr int BROWS   = BN * GATES;
    constexpr int ROWS    = (MODE == 2) ? N_NODES : NT;

    extern __shared__ uint32_t smu[];
    uint32_t* Ah = smu;
    uint32_t* Al = Ah + BM * LDK;
    uint32_t* Bh = Al + BM * LDK;
    uint32_t* Bl = Bh + BROWS * LDK;

    const float* A  = (MODE == 0) ? g_ins_all : (MODE == 1) ? g_H_all : g_hid;
    const float* Wm = (MODE == 0) ? g_ws1 : Wg;

    int tid = threadIdx.x;
    int rowBase = blockIdx.y * BM;
    int colBase = blockIdx.x * BN;

    // ---- stage A tile: fp32 -> packed bf16 hi/lo ----
    for (int idx = tid; idx < BM * (K / 4); idx += 256) {
        int r = idx / (K / 4), c4 = idx % (K / 4);
        int gr = rowBase + r;
        float4 v = make_float4(0.f, 0.f, 0.f, 0.f);
        if (gr < ROWS) v = *(const float4*)(A + (size_t)gr * K + c4 * 4);
        uint32_t lo0, lo1;
        uint32_t hi0 = pack_split(v.x, v.y, lo0);
        uint32_t hi1 = pack_split(v.z, v.w, lo1);
        int j = r * LDK + c4 * 2;
        Ah[j] = hi0; Ah[j + 1] = hi1;
        Al[j] = lo0; Al[j + 1] = lo1;
    }
    // ---- stage B tile(s) ----
    for (int idx = tid; idx < BROWS * (K / 4); idx += 256) {
        int r = idx / (K / 4), c4 = idx % (K / 4);
        int gr;
        if (MODE == 2) { int gate = r / BN, ln = r % BN; gr = gate * HT + colBase + ln; }
        else           { gr = colBase + r; }
        float4 v = *(const float4*)(Wm + (size_t)gr * K + c4 * 4);
        uint32_t lo0, lo1;
        uint32_t hi0 = pack_split(v.x, v.y, lo0);
        uint32_t hi1 = pack_split(v.z, v.w, lo1);
        int j = r * LDK + c4 * 2;
        Bh[j] = hi0; Bh[j + 1] = hi1;
        Bl[j] = lo0; Bl[j + 1] = lo1;
    }
    __syncthreads();

    int warp = tid >> 5, lane = tid & 31;
    int wm = warp / WARPS_N, wn = warp % WARPS_N;
    int g = lane >> 2, tg = lane & 3;
    int m0 = wm * WM, n0 = wn * WN;

    float acc[GATES][MF][NF][4] = {};

#pragma unroll
    for (int kk = 0; kk < K2; kk += 8) {           // 16 k-elements per step
        uint32_t ah[MF][4], al[MF][4];
#pragma unroll
        for (int mf = 0; mf < MF; mf++) {
            int base = (m0 + 16 * mf + g) * LDK + kk + tg;
            ah[mf][0] = Ah[base];            al[mf][0] = Al[base];
            ah[mf][1] = Ah[base + 8 * LDK];  al[mf][1] = Al[base + 8 * LDK];
            ah[mf][2] = Ah[base + 4];        al[mf][2] = Al[base + 4];
            ah[mf][3] = Ah[base + 8 * LDK + 4]; al[mf][3] = Al[base + 8 * LDK + 4];
        }
#pragma unroll
        for (int gt = 0; gt < GATES; gt++) {
#pragma unroll
            for (int nf = 0; nf < NF; nf++) {
                int bb = (gt * BN + n0 + 8 * nf + g) * LDK + kk + tg;
                uint32_t bh0 = Bh[bb], bh1 = Bh[bb + 4];
                uint32_t bl0 = Bl[bb], bl1 = Bl[bb + 4];
#pragma unroll
                for (int mf = 0; mf < MF; mf++) {
                    mma16(acc[gt][mf][nf], al[mf], bh0, bh1);   // small terms first
                    mma16(acc[gt][mf][nf], ah[mf], bl0, bl1);
                    mma16(acc[gt][mf][nf], ah[mf], bh0, bh1);
                }
            }
        }
    }

    if (MODE == 0) {
        // ---- +bias into smem, then fused LN+relu ----
        __syncthreads();
        float* S = (float*)smu;                // 128 x 68 floats (fits in Ah)
#pragma unroll
        for (int mf = 0; mf < MF; mf++)
#pragma unroll
            for (int nf = 0; nf < NF; nf++) {
                int r = m0 + 16 * mf + g;
                int c = n0 + 8 * nf + 2 * tg;
                S[r * 68 + c]           = acc[0][mf][nf][0] + bias[c];
                S[r * 68 + c + 1]       = acc[0][mf][nf][1] + bias[c + 1];
                S[(r + 8) * 68 + c]     = acc[0][mf][nf][2] + bias[c];
                S[(r + 8) * 68 + c + 1] = acc[0][mf][nf][3] + bias[c + 1];
            }
        __syncthreads();
#pragma unroll
        for (int i = 0; i < 16; i++) {
            int r = warp * 16 + i;
            float v0 = S[r * 68 + lane];
            float v1 = S[r * 68 + lane + 32];
            float mu = warp_sum(v0 + v1) * (1.f / 64.f);
            float d0 = v0 - mu, d1 = v1 - mu;
            float var = warp_sum(d0 * d0 + d1 * d1) * (1.f / 64.f);
            float inv = rsqrtf(var + LN_EPS);
            size_t rowg = (size_t)rowBase + r;
            g_H_all[rowg * HG + lane]      = fmaxf(d0 * inv * p0[lane]      + p1[lane], 0.f);
            g_H_all[rowg * HG + lane + 32] = fmaxf(d1 * inv * p0[lane + 32] + p1[lane + 32], 0.f);
        }
    } else if (MODE == 1) {
        // ---- +bias, store gi (NT multiple of BM: no row guards) ----
#pragma unroll
        for (int mf = 0; mf < MF; mf++)
#pragma unroll
            for (int nf = 0; nf < NF; nf++) {
                size_t r = (size_t)rowBase + m0 + 16 * mf + g;
                int c = colBase + n0 + 8 * nf + 2 * tg;
                float2 w0 = make_float2(acc[0][mf][nf][0] + bias[c],
                                        acc[0][mf][nf][1] + bias[c + 1]);
                float2 w1 = make_float2(acc[0][mf][nf][2] + bias[c],
                                        acc[0][mf][nf][3] + bias[c + 1]);
                *(float2*)(g_gi_all + r * G3 + c)       = w0;
                *(float2*)(g_gi_all + (r + 8) * G3 + c) = w1;
            }
    } else {
        // ---- fused GRU gates: h = (1-z)*n + z*h ----
#pragma unroll
        for (int mf = 0; mf < MF; mf++)
#pragma unroll
            for (int nf = 0; nf < NF; nf++) {
#pragma unroll
                for (int half = 0; half < 2; half++) {
                    int node = rowBase + m0 + 16 * mf + g + half * 8;
                    if (node >= N_NODES) continue;
                    int c = colBase + n0 + 8 * nf + 2 * tg;
                    const float* gi = g_gi_all + ((size_t)t * N_NODES + node) * G3;
                    float2 gir = *(const float2*)(gi + c);
                    float2 giz = *(const float2*)(gi + 128 + c);
                    float2 gin = *(const float2*)(gi + 256 + c);
                    float hr0 = acc[0][mf][nf][half * 2 + 0] + bias[c];
                    float hr1 = acc[0][mf][nf][half * 2 + 1] + bias[c + 1];
                    float hz0 = acc[1][mf][nf][half * 2 + 0] + bias[128 + c];
                    float hz1 = acc[1][mf][nf][half * 2 + 1] + bias[128 + c + 1];
                    float hn0 = acc[2][mf][nf][half * 2 + 0] + bias[256 + c];
                    float hn1 = acc[2][mf][nf][half * 2 + 1] + bias[256 + c + 1];
                    float* hid = g_hid + (size_t)node * HT + c;
                    float2 h = *(float2*)hid;
                    float r0 = 1.f / (1.f + __expf(-(gir.x + hr0)));
                    float r1 = 1.f / (1.f + __expf(-(gir.y + hr1)));
                    float z0 = 1.f / (1.f + __expf(-(giz.x + hz0)));
                    float z1 = 1.f / (1.f + __expf(-(giz.y + hz1)));
                    float n0v = tanhf(gin.x + r0 * hn0);
                    float n1v = tanhf(gin.y + r1 * hn1);
                    h.x = (1.f - z0) * n0v + z0 * h.x;
                    h.y = (1.f - z1) * n1v + z1 * h.y;
                    *(float2*)hid = h;
                }
            }
    }
}

// ------------------- GRU t=0 closed form (h=0): h1 = (1-z)*tanh(gin + r*bhh_n)
__global__ void k_gates0(const float* __restrict__ bhh) {
    int idx = blockIdx.x * blockDim.x + threadIdx.x;
    if (idx >= N_NODES * HT) return;
    int n = idx >> 7, j = idx & 127;
    const float* gi = g_gi_all + (size_t)n * G3;   // t = 0
    float r = 1.f / (1.f + __expf(-(gi[j] + bhh[j])));
    float z = 1.f / (1.f + __expf(-(gi[128 + j] + bhh[128 + j])));
    float nn = tanhf(gi[256 + j] + r * bhh[256 + j]);
    g_hid[idx] = (1.f - z) * nn;
}

// ------------------- output head ---------------------------------------------
__global__ void k_head(const float* __restrict__ W, const float* __restrict__ b,
                       float* __restrict__ y) {
    int warp = (blockIdx.x * blockDim.x + threadIdx.x) >> 5;
    int lane = threadIdx.x & 31;
    if (warp >= N_NODES) return;
    float acc = 0.f;
#pragma unroll
    for (int i = 0; i < 4; i++) {
        int j = lane + 32 * i;
        acc += g_hid[warp * HT + j] * W[j];
    }
    acc = warp_sum(acc);
    if (lane == 0) y[warp] = acc + b[0];
}

// ------------------------- launch ---------------------------------------------
extern "C" void kernel_launch(void* const* d_in, const int* in_sizes, int n_in,
                              void* d_out, int out_size) {
    const float* x_seq = (const float*)d_in[0];
    const int*   ei    = (const int*)d_in[1];
    const float* W_l0  = (const float*)d_in[2];
    const float* W_r0  = (const float*)d_in[3];
    const float* b0    = (const float*)d_in[4];
    const float* ln0g  = (const float*)d_in[5];
    const float* ln0b  = (const float*)d_in[6];
    const float* W_l1  = (const float*)d_in[7];
    const float* W_r1  = (const float*)d_in[8];
    const float* b1    = (const float*)d_in[9];
    const float* ln1g  = (const float*)d_in[10];
    const float* ln1b  = (const float*)d_in[11];
    const float* Wih   = (const float*)d_in[12];
    const float* Whh   = (const float*)d_in[13];
    const float* bih   = (const float*)d_in[14];
    const float* bhh   = (const float*)d_in[15];
    const float* headW = (const float*)d_in[16];
    const float* headb = (const float*)d_in[17];
    float* y = (float*)d_out;

    const int SMEM0 = (128 + 64)  * 68 * 2 * 4;   // 104448
    const int SMEM1 = (128 + 192) * 36 * 2 * 4;   //  92160
    const int SMEM2 = (128 + 192) * 68 * 2 * 4;   // 174080
    cudaFuncSetAttribute(k_mma<0>, cudaFuncAttributeMaxDynamicSharedMemorySize, SMEM0);
    cudaFuncSetAttribute(k_mma<1>, cudaFuncAttributeMaxDynamicSharedMemorySize, SMEM1);
    cudaFuncSetAttribute(k_mma<2>, cudaFuncAttributeMaxDynamicSharedMemorySize, SMEM2);

    // CSR build (k_scan re-zeroes cnt/fill for graph replays)
    k_hist<<<(N_EDGES + 255) / 256, 256>>>(ei);
    k_scan<<<1, 1024>>>();
    k_scatter<<<(N_EDGES + 255) / 256, 256>>>(ei);

    // phase A (order chosen so ncu's capture window lands on stack0/agg1)
    dim3 gridA((N_NODES + 7) / 8, T_STEPS);
    k_stack0_all<<<gridA, 256>>>(x_seq, W_l0, W_r0, b0, ln0g, ln0b);
    k_prep_ws1<<<(HG * 2 * HG + 255) / 256, 256>>>(W_l1, W_r1);
    k_agg1_all<<<gridA, 256>>>();

    k_mma<0><<<dim3(1, NT / 128), 256, SMEM0>>>(nullptr, b1, ln1g, ln1b, 0);
    k_mma<1><<<dim3(G3 / 192, NT / 128), 256, SMEM1>>>(Wih, bih, nullptr, nullptr, 0);

    // phase B: t=0 closed form, then 15 fused GEMM+gate steps
    k_gates0<<<(N_NODES * HT + 255) / 256, 256>>>(bhh);
    int gridGH = (N_NODES + 127) / 128;   // 157
    for (int t = 1; t < T_STEPS; t++)
        k_mma<2><<<dim3(2, gridGH), 256, SMEM2>>>(Whh, bhh, nullptr, nullptr, t);

    k_head<<<(N_NODES * 32 + 255) / 256, 256>>>(headW, headb, y);
}

// round 9
// speedup vs baseline: 1.4667x; 1.1351x over previous
#include <cuda_runtime.h>
#include <math.h>
#include <stdint.h>

#define N_NODES 20000
#define N_EDGES 320000
#define T_STEPS 16
#define HG 64
#define HT 128
#define G3 384
#define NT (N_NODES * T_STEPS)
#define LN_EPS 1e-5f

// ===================== scratch (static device globals) =======================
__device__ int   g_cnt[N_NODES];
__device__ int   g_fill[N_NODES];
__device__ int   g_rowptr[N_NODES + 1];
__device__ int   g_col[N_EDGES];
__device__ float g_h0_all[NT * HG];
__device__ float g_ins_all[NT * (2 * HG)];
__device__ float g_H_all[NT * HG];
__device__ float g_gi_all[NT * G3];
__device__ float g_hid[N_NODES * HT];

// pre-split packed-bf16 weights, fragment-contiguous: P[(rb*K2 + c)*8 + (row&7)]
__device__ uint32_t g_ws1h[8  * 64 * 8], g_ws1l[8  * 64 * 8];   // ws1: 64 x K2=64
__device__ uint32_t g_wihh[48 * 32 * 8], g_wihl[48 * 32 * 8];   // Wih: 384 x K2=32
__device__ uint32_t g_whhh[48 * 64 * 8], g_whhl[48 * 64 * 8];   // Whh: 384 x K2=64

__device__ __forceinline__ float warp_sum(float v) {
#pragma unroll
    for (int o = 16; o; o >>= 1) v += __shfl_xor_sync(0xFFFFFFFFu, v, o);
    return v;
}

// bf16x2 split: returns packed hi pair, writes packed lo pair (lo = v - hi)
__device__ __forceinline__ uint32_t pack_split(float x0, float x1, uint32_t& lo) {
    uint32_t hi;
    asm("cvt.rn.bf16x2.f32 %0, %1, %2;" : "=r"(hi) : "f"(x1), "f"(x0));
    float h0 = __uint_as_float(hi << 16);
    float h1 = __uint_as_float(hi & 0xFFFF0000u);
    float l0 = x0 - h0, l1 = x1 - h1;
    asm("cvt.rn.bf16x2.f32 %0, %1, %2;" : "=r"(lo) : "f"(l1), "f"(l0));
    return hi;
}

// m16n8k16 bf16 MMA (sm_80+ generic PTX)
__device__ __forceinline__ void mma16(float* d, const uint32_t* a, uint32_t b0, uint32_t b1) {
    asm volatile(
        "mma.sync.aligned.m16n8k16.row.col.f32.bf16.bf16.f32 "
        "{%0,%1,%2,%3}, {%4,%5,%6,%7}, {%8,%9}, {%0,%1,%2,%3};"
        : "+f"(d[0]), "+f"(d[1]), "+f"(d[2]), "+f"(d[3])
        : "r"(a[0]), "r"(a[1]), "r"(a[2]), "r"(a[3]), "r"(b0), "r"(b1));
}

// ------------------------- CSR build -----------------------------------------
__global__ void k_hist(const int* __restrict__ ei) {
    int e = blockIdx.x * blockDim.x + threadIdx.x;
    if (e < N_EDGES) atomicAdd(&g_cnt[ei[N_EDGES + e]], 1);
}

__global__ void k_scan() {
    __shared__ int sh[1024];
    __shared__ int base;
    int tid = threadIdx.x;
    if (tid == 0) { base = 0; g_rowptr[0] = 0; }
    __syncthreads();
    for (int start = 0; start < N_NODES; start += 1024) {
        int i = start + tid;
        int v = (i < N_NODES) ? g_cnt[i] : 0;
        sh[tid] = v;
        __syncthreads();
        for (int off = 1; off < 1024; off <<= 1) {
            int t = (tid >= off) ? sh[tid - off] : 0;
            __syncthreads();
            sh[tid] += t;
            __syncthreads();
        }
        if (i < N_NODES) g_rowptr[i + 1] = base + sh[tid];
        __syncthreads();
        if (tid == 1023) base += sh[1023];
        __syncthreads();
    }
    for (int i = tid; i < N_NODES; i += 1024) { g_cnt[i] = 0; g_fill[i] = 0; }
}

__global__ void k_scatter(const int* __restrict__ ei) {
    int e = blockIdx.x * blockDim.x + threadIdx.x;
    if (e >= N_EDGES) return;
    int d = ei[N_EDGES + e];
    int p = atomicAdd(&g_fill[d], 1);
    g_col[g_rowptr[d] + p] = ei[e];
}

// ------------------- weight pre-split kernels ---------------------------------
// Destinations are selected IN DEVICE CODE (GB300/ATS trap: passing __device__
// symbols as kernel args from host silently targets the host shadow copy).
__global__ void k_prep_ws1(const float* __restrict__ Wl1, const float* __restrict__ Wr1) {
    int idx = blockIdx.x * blockDim.x + threadIdx.x;   // 64 * 64
    if (idx >= 64 * 64) return;
    int m = idx >> 6, c = idx & 63;
    int k0 = 2 * c;
    float v0 = (k0 < 64) ? Wl1[k0 * 64 + m] : Wr1[(k0 - 64) * 64 + m];
    float v1 = (k0 + 1 < 64) ? Wl1[(k0 + 1) * 64 + m] : Wr1[(k0 - 63) * 64 + m];
    uint32_t lo, hi = pack_split(v0, v1, lo);
    int o = ((m >> 3) * 64 + c) * 8 + (m & 7);
    g_ws1h[o] = hi; g_ws1l[o] = lo;
}

template <int WSEL, int M, int K>
__global__ void k_prep_w(const float* __restrict__ W) {
    uint32_t* __restrict__ Ph = (WSEL == 0) ? g_wihh : g_whhh;
    uint32_t* __restrict__ Pl = (WSEL == 0) ? g_wihl : g_whhl;
    int idx = blockIdx.x * blockDim.x + threadIdx.x;   // M * K/2
    if (idx >= M * (K / 2)) return;
    int row = idx / (K / 2), c = idx % (K / 2);
    float v0 = W[row * K + 2 * c], v1 = W[row * K + 2 * c + 1];
    uint32_t lo, hi = pack_split(v0, v1, lo);
    int o = ((row >> 3) * (K / 2) + c) * 8 + (row & 7);
    Ph[o] = hi; Pl[o] = lo;
}

// ------------------- layer 0 (batched): agg + SAGE + LN + relu ----------------
__global__ void k_stack0_all(const float* __restrict__ x_seq,
                             const float* __restrict__ Wl, const float* __restrict__ Wr,
                             const float* __restrict__ b0,
                             const float* __restrict__ g, const float* __restrict__ beta) {
    int t = blockIdx.y;
    int n = blockIdx.x * 8 + (threadIdx.x >> 5);
    int lane = threadIdx.x & 31;
    if (n >= N_NODES) return;
    const float* xt = x_seq + t * N_NODES;
    int beg = g_rowptr[n], end = g_rowptr[n + 1];
    float acc = 0.f;
    for (int i = beg + lane; i < end; i += 32) acc += xt[g_col[i]];
    acc = warp_sum(acc);
    float deg = fmaxf((float)(end - beg), 1.f);
    float agg = acc / deg;
    float xv = xt[n];
    float v0 = agg * Wl[lane]      + xv * Wr[lane]      + b0[lane];
    float v1 = agg * Wl[lane + 32] + xv * Wr[lane + 32] + b0[lane + 32];
    float mu = warp_sum(v0 + v1) * (1.f / 64.f);
    float d0 = v0 - mu, d1 = v1 - mu;
    float var = warp_sum(d0 * d0 + d1 * d1) * (1.f / 64.f);
    float inv = rsqrtf(var + LN_EPS);
    float h0a = fmaxf(d0 * inv * g[lane]      + beta[lane], 0.f);
    float h0b = fmaxf(d1 * inv * g[lane + 32] + beta[lane + 32], 0.f);
    size_t row = (size_t)t * N_NODES + n;
    g_h0_all[row * HG + lane]      = h0a;
    g_h0_all[row * HG + lane + 32] = h0b;
    g_ins_all[row * 128 + 64 + lane]      = h0a;
    g_ins_all[row * 128 + 64 + lane + 32] = h0b;
}

// ------------------- layer 1 aggregate (batched, 2-way unrolled) --------------
__global__ void k_agg1_all() {
    int t = blockIdx.y;
    int n = blockIdx.x * 8 + (threadIdx.x >> 5);
    int lane = threadIdx.x & 31;
    if (n >= N_NODES) return;
    const float* h0t = g_h0_all + (size_t)t * N_NODES * HG;
    int beg = g_rowptr[n], end = g_rowptr[n + 1];
    float a0 = 0.f, a1 = 0.f, c0 = 0.f, c1 = 0.f;
    int i = beg;
    for (; i + 1 < end; i += 2) {
        int s0 = g_col[i], s1 = g_col[i + 1];
        a0 += h0t[s0 * HG + lane];
        a1 += h0t[s0 * HG + lane + 32];
        c0 += h0t[s1 * HG + lane];
        c1 += h0t[s1 * HG + lane + 32];
    }
    if (i < end) {
        int s = g_col[i];
        a0 += h0t[s * HG + lane];
        a1 += h0t[s * HG + lane + 32];
    }
    a0 += c0; a1 += c1;
    float inv = 1.f / fmaxf((float)(end - beg), 1.f);
    size_t row = (size_t)t * N_NODES + n;
    g_ins_all[row * 128 + lane]      = a0 * inv;
    g_ins_all[row * 128 + lane + 32] = a1 * inv;
}

// ===================== bf16x3 mma.sync GEMM kernels ===========================
// A tile staged+split in smem; B fragments loaded directly from pre-split global.
// MODE 0: S = ins_all(NTx128) @ ws1^T(64x128);  epilogue: +b1, LN, relu -> g_H_all
// MODE 1: gi = H_all(NTx64) @ Wih^T(384x64);    epilogue: +bih -> g_gi_all
// MODE 2: gh = hid(Nx128) @ Whh^T(384x128);     epilogue: fused GRU -> g_hid
template <int MODE>
__global__ void __launch_bounds__(256)
k_mma(const float* __restrict__ bias,
      const float* __restrict__ p0, const float* __restrict__ p1, int t) {
    constexpr int K       = (MODE == 1) ? 64 : 128;
    constexpr int K2      = K / 2;
    constexpr int LDK     = K2 + 4;                    // LDK%32==4 -> conflict-free
    constexpr int GATES   = (MODE == 2) ? 3 : 1;
    constexpr int BM      = 128;
    constexpr int BN      = (MODE == 1) ? 128 : 64;
    constexpr int WARPS_N = (MODE == 0) ? 2 : 4;
    constexpr int WM      = (MODE == 0) ? 32 : 64;
    constexpr int WN      = BN / WARPS_N;
    constexpr int MF      = WM / 16;
    constexpr int NF      = WN / 8;
    constexpr int ROWS    = (MODE == 2) ? N_NODES : NT;

    extern __shared__ uint32_t smu[];
    uint32_t* Ah = smu;
    uint32_t* Al = Ah + BM * LDK;

    const float* A = (MODE == 0) ? g_ins_all : (MODE == 1) ? g_H_all : g_hid;
    const uint32_t* __restrict__ BhG = (MODE == 0) ? g_ws1h : (MODE == 1) ? g_wihh : g_whhh;
    const uint32_t* __restrict__ BlG = (MODE == 0) ? g_ws1l : (MODE == 1) ? g_wihl : g_whhl;

    int tid = threadIdx.x;
    int rowBase = blockIdx.y * BM;
    int colBase = blockIdx.x * BN;

    // ---- stage A tile: fp32 -> packed bf16 hi/lo in smem ----
    for (int idx = tid; idx < BM * (K / 4); idx += 256) {
        int r = idx / (K / 4), c4 = idx % (K / 4);
        int gr = rowBase + r;
        float4 v = make_float4(0.f, 0.f, 0.f, 0.f);
        if (gr < ROWS) v = *(const float4*)(A + (size_t)gr * K + c4 * 4);
        uint32_t lo0, lo1;
        uint32_t hi0 = pack_split(v.x, v.y, lo0);
        uint32_t hi1 = pack_split(v.z, v.w, lo1);
        int j = r * LDK + c4 * 2;
        Ah[j] = hi0; Ah[j + 1] = hi1;
        Al[j] = lo0; Al[j + 1] = lo1;
    }
    __syncthreads();

    int warp = tid >> 5, lane = tid & 31;
    int wm = warp / WARPS_N, wn = warp % WARPS_N;
    int g = lane >> 2, tg = lane & 3;
    int m0 = wm * WM, n0 = wn * WN;

    float acc[GATES][MF][NF][4] = {};

#pragma unroll
    for (int kk = 0; kk < K2; kk += 8) {               // 16 k-elements per step
        uint32_t ah[MF][4], al[MF][4];
#pragma unroll
        for (int mf = 0; mf < MF; mf++) {
            int base = (m0 + 16 * mf + g) * LDK + kk + tg;
            ah[mf][0] = Ah[base];               al[mf][0] = Al[base];
            ah[mf][1] = Ah[base + 8 * LDK];     al[mf][1] = Al[base + 8 * LDK];
            ah[mf][2] = Ah[base + 4];           al[mf][2] = Al[base + 4];
            ah[mf][3] = Ah[base + 8 * LDK + 4]; al[mf][3] = Al[base + 8 * LDK + 4];
        }
#pragma unroll
        for (int gt = 0; gt < GATES; gt++) {
#pragma unroll
            for (int nf = 0; nf < NF; nf++) {
                int nrow = ((MODE == 2) ? gt * HT : 0) + colBase + n0 + 8 * nf;
                int fo = ((nrow >> 3) * K2 + kk + tg) * 8 + g;
                uint32_t bh0 = BhG[fo], bh1 = BhG[fo + 32];
                uint32_t bl0 = BlG[fo], bl1 = BlG[fo + 32];
#pragma unroll
                for (int mf = 0; mf < MF; mf++) {
                    mma16(acc[gt][mf][nf], al[mf], bh0, bh1);   // small terms first
                    mma16(acc[gt][mf][nf], ah[mf], bl0, bl1);
                    mma16(acc[gt][mf][nf], ah[mf], bh0, bh1);
                }
            }
        }
    }

    if (MODE == 0) {
        // ---- +bias into smem, then fused LN+relu ----
        __syncthreads();
        float* S = (float*)smu;                // 128 x 68 floats (fits in Ah)
#pragma unroll
        for (int mf = 0; mf < MF; mf++)
#pragma unroll
            for (int nf = 0; nf < NF; nf++) {
                int r = m0 + 16 * mf + g;
                int c = n0 + 8 * nf + 2 * tg;
                S[r * 68 + c]           = acc[0][mf][nf][0] + bias[c];
                S[r * 68 + c + 1]       = acc[0][mf][nf][1] + bias[c + 1];
                S[(r + 8) * 68 + c]     = acc[0][mf][nf][2] + bias[c];
                S[(r + 8) * 68 + c + 1] = acc[0][mf][nf][3] + bias[c + 1];
            }
        __syncthreads();
#pragma unroll
        for (int i = 0; i < 16; i++) {
            int r = warp * 16 + i;
            float v0 = S[r * 68 + lane];
            float v1 = S[r * 68 + lane + 32];
            float mu = warp_sum(v0 + v1) * (1.f / 64.f);
            float d0 = v0 - mu, d1 = v1 - mu;
            float var = warp_sum(d0 * d0 + d1 * d1) * (1.f / 64.f);
            float inv = rsqrtf(var + LN_EPS);
            size_t rowg = (size_t)rowBase + r;
            g_H_all[rowg * HG + lane]      = fmaxf(d0 * inv * p0[lane]      + p1[lane], 0.f);
            g_H_all[rowg * HG + lane + 32] = fmaxf(d1 * inv * p0[lane + 32] + p1[lane + 32], 0.f);
        }
    } else if (MODE == 1) {
        // ---- +bias, store gi (NT multiple of BM: no row guards) ----
#pragma unroll
        for (int mf = 0; mf < MF; mf++)
#pragma unroll
            for (int nf = 0; nf < NF; nf++) {
                size_t r = (size_t)rowBase + m0 + 16 * mf + g;
                int c = colBase + n0 + 8 * nf + 2 * tg;
                float2 w0 = make_float2(acc[0][mf][nf][0] + bias[c],
                                        acc[0][mf][nf][1] + bias[c + 1]);
                float2 w1 = make_float2(acc[0][mf][nf][2] + bias[c],
                                        acc[0][mf][nf][3] + bias[c + 1]);
                *(float2*)(g_gi_all + r * G3 + c)       = w0;
                *(float2*)(g_gi_all + (r + 8) * G3 + c) = w1;
            }
    } else {
        // ---- fused GRU gates: h = (1-z)*n + z*h ----
#pragma unroll
        for (int mf = 0; mf < MF; mf++)
#pragma unroll
            for (int nf = 0; nf < NF; nf++) {
#pragma unroll
                for (int half = 0; half < 2; half++) {
                    int node = rowBase + m0 + 16 * mf + g + half * 8;
                    if (node >= N_NODES) continue;
                    int c = colBase + n0 + 8 * nf + 2 * tg;
                    const float* gi = g_gi_all + ((size_t)t * N_NODES + node) * G3;
                    float2 gir = *(const float2*)(gi + c);
                    float2 giz = *(const float2*)(gi + 128 + c);
                    float2 gin = *(const float2*)(gi + 256 + c);
                    float hr0 = acc[0][mf][nf][half * 2 + 0] + bias[c];
                    float hr1 = acc[0][mf][nf][half * 2 + 1] + bias[c + 1];
                    float hz0 = acc[1][mf][nf][half * 2 + 0] + bias[128 + c];
                    float hz1 = acc[1][mf][nf][half * 2 + 1] + bias[128 + c + 1];
                    float hn0 = acc[2][mf][nf][half * 2 + 0] + bias[256 + c];
                    float hn1 = acc[2][mf][nf][half * 2 + 1] + bias[256 + c + 1];
                    float* hid = g_hid + (size_t)node * HT + c;
                    float2 h = *(float2*)hid;
                    float r0 = 1.f / (1.f + __expf(-(gir.x + hr0)));
                    float r1 = 1.f / (1.f + __expf(-(gir.y + hr1)));
                    float z0 = 1.f / (1.f + __expf(-(giz.x + hz0)));
                    float z1 = 1.f / (1.f + __expf(-(giz.y + hz1)));
                    float n0v = tanhf(gin.x + r0 * hn0);
                    float n1v = tanhf(gin.y + r1 * hn1);
                    h.x = (1.f - z0) * n0v + z0 * h.x;
                    h.y = (1.f - z1) * n1v + z1 * h.y;
                    *(float2*)hid = h;
                }
            }
    }
}

// ------------------- GRU t=0 closed form (h=0) --------------------------------
__global__ void k_gates0(const float* __restrict__ bhh) {
    int idx = blockIdx.x * blockDim.x + threadIdx.x;
    if (idx >= N_NODES * HT) return;
    int n = idx >> 7, j = idx & 127;
    const float* gi = g_gi_all + (size_t)n * G3;   // t = 0
    float r = 1.f / (1.f + __expf(-(gi[j] + bhh[j])));
    float z = 1.f / (1.f + __expf(-(gi[128 + j] + bhh[128 + j])));
    float nn = tanhf(gi[256 + j] + r * bhh[256 + j]);
    g_hid[idx] = (1.f - z) * nn;
}

// ------------------- output head -----------------------------------------------
__global__ void k_head(const float* __restrict__ W, const float* __restrict__ b,
                       float* __restrict__ y) {
    int warp = (blockIdx.x * blockDim.x + threadIdx.x) >> 5;
    int lane = threadIdx.x & 31;
    if (warp >= N_NODES) return;
    float acc = 0.f;
#pragma unroll
    for (int i = 0; i < 4; i++) {
        int j = lane + 32 * i;
        acc += g_hid[warp * HT + j] * W[j];
    }
    acc = warp_sum(acc);
    if (lane == 0) y[warp] = acc + b[0];
}

// ------------------------- launch ------------------------------------------------
extern "C" void kernel_launch(void* const* d_in, const int* in_sizes, int n_in,
                              void* d_out, int out_size) {
    const float* x_seq = (const float*)d_in[0];
    const int*   ei    = (const int*)d_in[1];
    const float* W_l0  = (const float*)d_in[2];
    const float* W_r0  = (const float*)d_in[3];
    const float* b0    = (const float*)d_in[4];
    const float* ln0g  = (const float*)d_in[5];
    const float* ln0b  = (const float*)d_in[6];
    const float* W_l1  = (const float*)d_in[7];
    const float* W_r1  = (const float*)d_in[8];
    const float* b1    = (const float*)d_in[9];
    const float* ln1g  = (const float*)d_in[10];
    const float* ln1b  = (const float*)d_in[11];
    const float* Wih   = (const float*)d_in[12];
    const float* Whh   = (const float*)d_in[13];
    const float* bih   = (const float*)d_in[14];
    const float* bhh   = (const float*)d_in[15];
    const float* headW = (const float*)d_in[16];
    const float* headb = (const float*)d_in[17];
    float* y = (float*)d_out;

    const int SMEM0 = 128 * 68 * 2 * 4;   // 69632
    const int SMEM1 = 128 * 36 * 2 * 4;   // 36864
    const int SMEM2 = 128 * 68 * 2 * 4;   // 69632
    cudaFuncSetAttribute(k_mma<0>, cudaFuncAttributeMaxDynamicSharedMemorySize, SMEM0);
    cudaFuncSetAttribute(k_mma<1>, cudaFuncAttributeMaxDynamicSharedMemorySize, SMEM1);
    cudaFuncSetAttribute(k_mma<2>, cudaFuncAttributeMaxDynamicSharedMemorySize, SMEM2);

    // CSR build (k_scan re-zeroes cnt/fill for graph replays)
    k_hist<<<(N_EDGES + 255) / 256, 256>>>(ei);
    k_scan<<<1, 1024>>>();
    k_scatter<<<(N_EDGES + 255) / 256, 256>>>(ei);

    // phase A
    dim3 gridA((N_NODES + 7) / 8, T_STEPS);
    k_stack0_all<<<gridA, 256>>>(x_seq, W_l0, W_r0, b0, ln0g, ln0b);
    k_prep_ws1<<<(64 * 64 + 255) / 256, 256>>>(W_l1, W_r1);
    k_prep_w<0, G3, 64><<<(G3 * 32 + 255) / 256, 256>>>(Wih);
    k_prep_w<1, G3, 128><<<(G3 * 64 + 255) / 256, 256>>>(Whh);
    k_agg1_all<<<gridA, 256>>>();

    k_mma<0><<<dim3(1, NT / 128), 256, SMEM0>>>(b1, ln1g, ln1b, 0);
    k_mma<1><<<dim3(G3 / 128, NT / 128), 256, SMEM1>>>(bih, nullptr, nullptr, 0);

    // phase B: t=0 closed form, then 15 fused GEMM+gate steps
    k_gates0<<<(N_NODES * HT + 255) / 256, 256>>>(bhh);
    int gridGH = (N_NODES + 127) / 128;   // 157
    for (int t = 1; t < T_STEPS; t++)
        k_mma<2><<<dim3(2, gridGH), 256, SMEM2>>>(bhh, nullptr, nullptr, t);

    k_head<<<(N_NODES * 32 + 255) / 256, 256>>>(headW, headb, y);
}